// round 12
// baseline (speedup 1.0000x reference)
#include <cuda_runtime.h>
#include <cstdint>

// LIF-MC-Refrac (R12): two dedicated kernels.
//  K1 coupling: packed fp32 FFMA2 GEMM (R11 coupling verbatim) -> z, v, rho.
//    Alone on chip -> runs at the FFMA2 pipe floor, L1 uncontended.
//  K2 i-path: TF32 mma.sync, 128 thr/CTA, 255 regs, 64x64 warp tiles ->
//    1.5x less fragment smem traffic per FLOP -> i.

namespace {
constexpr int Bd = 4096;
constexpr int Hd = 2048;
constexpr int Kd = 2048;

constexpr int BM = 128, BN = 128, BK = 16;
constexpr int SSTR = BK + 4;          // mma smem row stride (20 words)
constexpr int AST  = BM + 4;          // coupling smem row stride (132 words)

constexpr float DT_TAU_MEM = 0.1f;
constexpr float DT_TAU_SYN = 0.2f;
constexpr float V_TH_C     = 1.0f;
constexpr float RHO_RST    = 5.0f;
}

// ---- packed f32x2 helpers ----
__device__ __forceinline__ unsigned long long packf2(float lo, float hi) {
    unsigned long long r;
    asm("mov.b64 %0, {%1, %2};" : "=l"(r) : "f"(lo), "f"(hi));
    return r;
}
__device__ __forceinline__ unsigned long long dupf2(float x) {
    unsigned long long r;
    asm("mov.b64 %0, {%1, %1};" : "=l"(r) : "f"(x));
    return r;
}
__device__ __forceinline__ void ffma2(unsigned long long& d,
                                      unsigned long long a, unsigned long long b) {
    asm("fma.rn.f32x2 %0, %1, %2, %0;" : "+l"(d) : "l"(a), "l"(b));
}
__device__ __forceinline__ void unpackf2(unsigned long long v, float& lo, float& hi) {
    asm("mov.b64 {%0, %1}, %2;" : "=f"(lo), "=f"(hi) : "l"(v));
}

__device__ __forceinline__ void mma_tf32(float& c0, float& c1, float& c2, float& c3,
                                         uint32_t a0, uint32_t a1, uint32_t a2, uint32_t a3,
                                         uint32_t b0, uint32_t b1)
{
    asm volatile(
        "mma.sync.aligned.m16n8k8.row.col.f32.tf32.tf32.f32 "
        "{%0,%1,%2,%3},{%4,%5,%6,%7},{%8,%9},{%0,%1,%2,%3};"
        : "+f"(c0), "+f"(c1), "+f"(c2), "+f"(c3)
        : "r"(a0), "r"(a1), "r"(a2), "r"(a3), "r"(b0), "r"(b1));
}

__device__ __forceinline__ void lif_elem(float v, float i, float rho, float couple,
                                         float& z_out, float& v_out, float& rho_out)
{
    float dv    = DT_TAU_MEM * ((0.0f - v) + i);
    float v_dec = (v + dv) + couple;
    float z     = (v_dec - V_TH_C) > 0.0f ? 1.0f : 0.0f;
    float v_new = (1.0f - z) * v_dec;
    float mask  = rho > 0.0f ? 1.0f : 0.0f;
    v_new = (1.0f - mask) * v_new + mask * v;
    z     = (1.0f - mask) * z;
    rho_out = (1.0f - z) * fmaxf(rho - mask, 0.0f) + z * RHO_RST;
    z_out = z;
    v_out = v_new;
}

// ================= K1: coupling GEMM (R11 coupling, standalone) ===============
__global__ void __launch_bounds__(256, 2) coupling_kernel(
    const float* __restrict__ A0, const float* __restrict__ W0,
    const float* __restrict__ vin, const float* __restrict__ iin,
    const float* __restrict__ rhoin,
    float* __restrict__ out_z, float* __restrict__ out_v, float* __restrict__ out_rho)
{
    __shared__ float As[BK * AST];
    __shared__ float Bs[BK * AST];

    const int bid = blockIdx.x;
    const int bx = bid & 15;
    const int by = bid >> 4;

    const int tid = threadIdx.x;
    const int tx = tid & 15;
    const int ty = tid >> 4;
    const int cA = tx * 4;
    const int cB = 64 + tx * 4;

    const int loadRow = tid >> 2;
    const int loadK   = (tid & 3) << 2;
    const int xs      = loadK & 8;
    const int sCol0   = loadRow ^ xs;
    const int sCol1   = sCol0 + 64;

    unsigned long long acc2[4][8];
#pragma unroll
    for (int a = 0; a < 4; ++a)
#pragma unroll
        for (int b = 0; b < 8; ++b) acc2[a][b] = 0ull;

    const float* aPtr = A0 + (size_t)(by * BM + loadRow) * Kd + loadK;
    const float* wPtr = W0 + (size_t)(bx * BN + loadRow) * Kd + loadK;

    float4 ra0 = *(const float4*)(aPtr);
    float4 ra1 = *(const float4*)(aPtr + (size_t)64 * Kd);
    float4 rb0 = *(const float4*)(wPtr);
    float4 rb1 = *(const float4*)(wPtr + (size_t)64 * Kd);

    for (int kt = 0; kt < Kd; kt += BK) {
        __syncthreads();
        As[(loadK + 0) * AST + sCol0] = ra0.x;
        As[(loadK + 1) * AST + sCol0] = ra0.y;
        As[(loadK + 2) * AST + sCol0] = ra0.z;
        As[(loadK + 3) * AST + sCol0] = ra0.w;
        As[(loadK + 0) * AST + sCol1] = ra1.x;
        As[(loadK + 1) * AST + sCol1] = ra1.y;
        As[(loadK + 2) * AST + sCol1] = ra1.z;
        As[(loadK + 3) * AST + sCol1] = ra1.w;
        Bs[(loadK + 0) * AST + sCol0] = rb0.x;
        Bs[(loadK + 1) * AST + sCol0] = rb0.y;
        Bs[(loadK + 2) * AST + sCol0] = rb0.z;
        Bs[(loadK + 3) * AST + sCol0] = rb0.w;
        Bs[(loadK + 0) * AST + sCol1] = rb1.x;
        Bs[(loadK + 1) * AST + sCol1] = rb1.y;
        Bs[(loadK + 2) * AST + sCol1] = rb1.z;
        Bs[(loadK + 3) * AST + sCol1] = rb1.w;
        __syncthreads();

        if (kt + BK < Kd) {
            aPtr += BK; wPtr += BK;
            ra0 = *(const float4*)(aPtr);
            ra1 = *(const float4*)(aPtr + (size_t)64 * Kd);
            rb0 = *(const float4*)(wPtr);
            rb1 = *(const float4*)(wPtr + (size_t)64 * Kd);
        }

#pragma unroll
        for (int k = 0; k < BK; ++k) {
            const int xk = k & 8;
            float4 a0 = *(const float4*)&As[k * AST + ((ty * 8) ^ xk)];
            float4 a1 = *(const float4*)&As[k * AST + (((ty * 8) ^ xk) + 4)];
            float4 b0 = *(const float4*)&Bs[k * AST + (cA ^ xk)];
            float4 b1 = *(const float4*)&Bs[k * AST + (64 + (cA ^ xk))];

            unsigned long long ap[4];
            ap[0] = packf2(a0.x, a0.y);
            ap[1] = packf2(a0.z, a0.w);
            ap[2] = packf2(a1.x, a1.y);
            ap[3] = packf2(a1.z, a1.w);

            float bf[8] = {b0.x, b0.y, b0.z, b0.w, b1.x, b1.y, b1.z, b1.w};
#pragma unroll
            for (int b = 0; b < 8; ++b) {
                unsigned long long bb = dupf2(bf[b]);
                ffma2(acc2[0][b], ap[0], bb);
                ffma2(acc2[1][b], ap[1], bb);
                ffma2(acc2[2][b], ap[2], bb);
                ffma2(acc2[3][b], ap[3], bb);
            }
        }
    }

    float acc[8][8];
#pragma unroll
    for (int p = 0; p < 4; ++p)
#pragma unroll
        for (int b = 0; b < 8; ++b)
            unpackf2(acc2[p][b], acc[2 * p][b], acc[2 * p + 1][b]);

    const int row0 = by * BM + ty * 8;
    const int colA = bx * BN + cA;
    const int colB = bx * BN + cB;
#pragma unroll
    for (int a = 0; a < 8; ++a) {
#pragma unroll
        for (int h = 0; h < 2; ++h) {
            const size_t base = (size_t)(row0 + a) * Hd + (h ? colB : colA);
            const int boff = h * 4;
            float4 vv = *(const float4*)(vin + base);
            float4 iv = *(const float4*)(iin + base);
            float4 rv = *(const float4*)(rhoin + base);
            float4 oz, ov, orh;
            lif_elem(vv.x, iv.x, rv.x, acc[a][boff + 0], oz.x, ov.x, orh.x);
            lif_elem(vv.y, iv.y, rv.y, acc[a][boff + 1], oz.y, ov.y, orh.y);
            lif_elem(vv.z, iv.z, rv.z, acc[a][boff + 2], oz.z, ov.z, orh.z);
            lif_elem(vv.w, iv.w, rv.w, acc[a][boff + 3], oz.w, ov.w, orh.w);
            *(float4*)(out_z   + base) = oz;
            *(float4*)(out_v   + base) = ov;
            *(float4*)(out_rho + base) = orh;
        }
    }
}

// ================= K2: i-path TF32 MMA, 128 thr, 64x64 warp tiles =============
// R11 position map: pos(k)=2f(a,c)+b, f0=[0,2,1,3], f1=[5,7,4,6].
__global__ void __launch_bounds__(128, 2) ipath_kernel(
    const float* __restrict__ A0, const float* __restrict__ W0,
    const float* __restrict__ A1, const float* __restrict__ W1,
    const float* __restrict__ iin, float* __restrict__ out_i)
{
    __shared__ uint32_t Ahi[BM * SSTR];
    __shared__ uint32_t Bhi[BN * SSTR];

    const int bid = blockIdx.x;
    const int bx = bid & 15;
    const int by = bid >> 4;

    const int tid  = threadIdx.x;
    const int warp = tid >> 5;
    const int lane = tid & 31;
    const int g    = lane >> 2;
    const int q    = lane & 3;
    const int wM   = warp >> 1;        // 0..1 -> 64 rows
    const int wN   = warp & 1;         // 0..1 -> 64 cols

    const int loadRow = tid >> 2;      // 0..31; rows {r, r+32, r+64, r+96}
    const int loadK   = (tid & 3) << 2;
    const int t       = tid & 3;
    const int ta_     = t >> 1;
    const int tb_     = t & 1;

    const int d0 = (ta_ ? 10 : 0) + tb_;
    const int d1 = (ta_ ? 14 : 4) + tb_;
    const int d2 = (ta_ ?  8 : 2) + tb_;
    const int d3 = (ta_ ? 12 : 6) + tb_;

    const int B0q  = ((q & 1) << 2) | (q & 2);
    const int off0 = B0q;
    const int off1 = 8 + (B0q ^ 2);

    float acc[4][8][4];                // 128 regs: warp tile 64x64
#pragma unroll
    for (int mt = 0; mt < 4; ++mt)
#pragma unroll
        for (int nt = 0; nt < 8; ++nt)
#pragma unroll
            for (int r = 0; r < 4; ++r) acc[mt][nt][r] = 0.0f;

#pragma unroll
    for (int p = 0; p < 2; ++p) {
        const float* Amat = (p == 0) ? A0 : A1;
        const float* Wmat = (p == 0) ? W0 : W1;
        const float* aPtr = Amat + (size_t)(by * BM + loadRow) * Kd + loadK;
        const float* wPtr = Wmat + (size_t)(bx * BN + loadRow) * Kd + loadK;

        uint4 ra[4], rb[4];
#pragma unroll
        for (int r = 0; r < 4; ++r) {
            ra[r] = *(const uint4*)(aPtr + (size_t)(32 * r) * Kd);
            rb[r] = *(const uint4*)(wPtr + (size_t)(32 * r) * Kd);
        }

        for (int kt = 0; kt < Kd; kt += BK) {
            __syncthreads();
#pragma unroll
            for (int r = 0; r < 4; ++r) {
                const int rr = (loadRow + 32 * r) * SSTR;
                Ahi[rr + d0] = ra[r].x;
                Ahi[rr + d1] = ra[r].y;
                Ahi[rr + d2] = ra[r].z;
                Ahi[rr + d3] = ra[r].w;
                Bhi[rr + d0] = rb[r].x;
                Bhi[rr + d1] = rb[r].y;
                Bhi[rr + d2] = rb[r].z;
                Bhi[rr + d3] = rb[r].w;
            }
            __syncthreads();

            if (kt + BK < Kd) {
                aPtr += BK; wPtr += BK;
#pragma unroll
                for (int r = 0; r < 4; ++r) {
                    ra[r] = *(const uint4*)(aPtr + (size_t)(32 * r) * Kd);
                    rb[r] = *(const uint4*)(wPtr + (size_t)(32 * r) * Kd);
                }
            }

#pragma unroll
            for (int ks = 0; ks < 2; ++ks) {
                const int kb = ks ? off1 : off0;
                uint2 bq[8];
#pragma unroll
                for (int nt = 0; nt < 8; ++nt)
                    bq[nt] = *(const uint2*)&Bhi[(wN * 64 + nt * 8 + g) * SSTR + kb];
#pragma unroll
                for (int mt = 0; mt < 4; ++mt) {
                    const int r0 = (wM * 64 + mt * 16 + g) * SSTR + kb;
                    uint2 tA = *(const uint2*)&Ahi[r0];
                    uint2 tC = *(const uint2*)&Ahi[r0 + 8 * SSTR];
#pragma unroll
                    for (int nt = 0; nt < 8; ++nt) {
                        float* c = acc[mt][nt];
                        mma_tf32(c[0], c[1], c[2], c[3],
                                 tA.x, tC.x, tA.y, tC.y, bq[nt].x, bq[nt].y);
                    }
                }
            }
        }
    }

#pragma unroll
    for (int mt = 0; mt < 4; ++mt) {
#pragma unroll
        for (int nt = 0; nt < 8; ++nt) {
            const float* c = acc[mt][nt];
            int row0 = by * BM + wM * 64 + mt * 16 + g;
            int col  = bx * BN + wN * 64 + nt * 8 + 2 * q;
            size_t idx0 = (size_t)row0 * Hd + col;
            size_t idx1 = idx0 + (size_t)8 * Hd;
            float2 i0 = *(const float2*)(iin + idx0);
            float2 i1 = *(const float2*)(iin + idx1);
            float2 o0, o1;
            o0.x = (i0.x - DT_TAU_SYN * i0.x) + c[0];
            o0.y = (i0.y - DT_TAU_SYN * i0.y) + c[1];
            o1.x = (i1.x - DT_TAU_SYN * i1.x) + c[2];
            o1.y = (i1.y - DT_TAU_SYN * i1.y) + c[3];
            *(float2*)(out_i + idx0) = o0;
            *(float2*)(out_i + idx1) = o1;
        }
    }
}

extern "C" void kernel_launch(void* const* d_in, const int* in_sizes, int n_in,
                              void* d_out, int out_size)
{
    const float* inp  = (const float*)d_in[0];
    const float* z    = (const float*)d_in[1];
    const float* v    = (const float*)d_in[2];
    const float* icur = (const float*)d_in[3];
    const float* rho  = (const float*)d_in[4];
    const float* Wi   = (const float*)d_in[5];
    const float* Wr   = (const float*)d_in[6];
    const float* g    = (const float*)d_in[7];

    float* out      = (float*)d_out;
    const size_t nBH = (size_t)Bd * Hd;

    // K2 first (tensor-bound, short), then K1 (FMA-bound) — order irrelevant
    ipath_kernel<<<512, 128>>>(inp, Wi, z, Wr, icur, out + 2 * nBH);
    coupling_kernel<<<512, 256>>>(v, g, v, icur, rho,
                                  out, out + nBH, out + 3 * nBH);
}